// round 4
// baseline (speedup 1.0000x reference)
#include <cuda_runtime.h>

#define DD   64
#define LL   3
#define NMAX 100000
#define EMAX 1200000

// ---------------- scratch (device globals: allocation-free) ----------------
__device__ float g_M[NMAX * DD];      // mlp(h) per node (message values)
__device__ float g_G[NMAX * DD];      // aggregated messages per node
__device__ float g_H[NMAX * DD];      // hidden state ping
__device__ float g_H2[NMAX * DD];     // hidden state pong
__device__ int   g_cnt[NMAX];         // per-node in-degree / scatter cursor
__device__ int   g_rowptr[NMAX + 1];  // CSR row pointers (by edge row / dst)
__device__ int   g_ecol[EMAX];        // CSR column indices (src node per edge)
__device__ int   g_bsums[1024];       // scan block sums

// ---------------- packed f32x2 helpers ----------------
__device__ __forceinline__ unsigned long long pack2(float a, float b) {
    unsigned long long r;
    asm("mov.b64 %0, {%1, %2};" : "=l"(r) : "f"(a), "f"(b));
    return r;
}
__device__ __forceinline__ void unpack2(unsigned long long v, float& a, float& b) {
    asm("mov.b64 {%0, %1}, %2;" : "=f"(a), "=f"(b) : "l"(v));
}
__device__ __forceinline__ void fma2(unsigned long long& d,
                                     unsigned long long a, unsigned long long b) {
    asm("fma.rn.f32x2 %0, %1, %2, %0;" : "+l"(d) : "l"(a), "l"(b));
}
__device__ __forceinline__ void lds_v2u64(unsigned addr,
                                          unsigned long long& a, unsigned long long& b) {
    asm("ld.shared.v2.u64 {%0, %1}, [%2];" : "=l"(a), "=l"(b) : "r"(addr));
}

// ---------------- CSR construction ----------------
__global__ void hist_kernel(const int* __restrict__ rows, int E) {
    int e = blockIdx.x * blockDim.x + threadIdx.x;
    if (e < E) atomicAdd(&g_cnt[rows[e]], 1);
}

__global__ void scan1_kernel(int n) {
    __shared__ int sh[1024];
    int i = blockIdx.x * 1024 + threadIdx.x;
    int v = (i < n) ? g_cnt[i] : 0;
    sh[threadIdx.x] = v;
    __syncthreads();
    for (int off = 1; off < 1024; off <<= 1) {
        int t = (threadIdx.x >= off) ? sh[threadIdx.x - off] : 0;
        __syncthreads();
        sh[threadIdx.x] += t;
        __syncthreads();
    }
    if (i < n) g_rowptr[i] = sh[threadIdx.x] - v;       // exclusive within block
    if (threadIdx.x == 1023) g_bsums[blockIdx.x] = sh[1023];
}

__global__ void scan2_kernel(int nb) {
    __shared__ int sh[1024];
    int v = (threadIdx.x < nb) ? g_bsums[threadIdx.x] : 0;
    sh[threadIdx.x] = v;
    __syncthreads();
    for (int off = 1; off < 1024; off <<= 1) {
        int t = (threadIdx.x >= off) ? sh[threadIdx.x - off] : 0;
        __syncthreads();
        sh[threadIdx.x] += t;
        __syncthreads();
    }
    if (threadIdx.x < nb) g_bsums[threadIdx.x] = sh[threadIdx.x] - v;  // exclusive
}

__global__ void scan3_kernel(int n, int E) {
    int i = blockIdx.x * blockDim.x + threadIdx.x;
    if (i < n) g_rowptr[i] += g_bsums[i >> 10];
    if (i == n) g_rowptr[n] = E;
}

__global__ void scatter_kernel(const int* __restrict__ rows,
                               const int* __restrict__ cols, int E) {
    int e = blockIdx.x * blockDim.x + threadIdx.x;
    if (e < E) {
        int r = rows[e];
        int pos = g_rowptr[r] + atomicAdd(&g_cnt[r], 1);
        g_ecol[pos] = cols[e];
    }
}

// ---------------- core GEMM stage: x <- act(x @ Wsm + bsm) ----------------
__device__ __forceinline__ void stage64(float (&x)[DD], const float* wsm,
                                        const float* bsm, bool do_relu) {
    unsigned wa = (unsigned)__cvta_generic_to_shared(wsm);
    unsigned long long acc[32];
#pragma unroll
    for (int j = 0; j < 32; j++) acc[j] = pack2(bsm[2 * j], bsm[2 * j + 1]);
#pragma unroll
    for (int k = 0; k < DD; k++) {
        unsigned long long xk = pack2(x[k], x[k]);
        unsigned rowa = wa + k * DD * 4;
#pragma unroll
        for (int j = 0; j < 16; j++) {
            unsigned long long a, b;
            lds_v2u64(rowa + j * 16, a, b);
            fma2(acc[2 * j], xk, a);
            fma2(acc[2 * j + 1], xk, b);
        }
    }
#pragma unroll
    for (int j = 0; j < 32; j++) {
        float a, b;
        unpack2(acc[j], a, b);
        x[2 * j]     = do_relu ? fmaxf(a, 0.0f) : a;
        x[2 * j + 1] = do_relu ? fmaxf(b, 0.0f) : b;
    }
}

__device__ __forceinline__ void load_weights(float* w1s, float* w2s,
                                             float* b1s, float* b2s,
                                             const float* W1, const float* W2,
                                             const float* B1, const float* B2) {
    const float4* w1v = (const float4*)W1;
    const float4* w2v = (const float4*)W2;
    float4* s1 = (float4*)w1s;
    float4* s2 = (float4*)w2s;
    for (int i = threadIdx.x; i < DD * DD / 4; i += blockDim.x) {
        s1[i] = w1v[i];
        s2[i] = w2v[i];
    }
    if (threadIdx.x < DD) {
        b1s[threadIdx.x] = B1[threadIdx.x];
        b2s[threadIdx.x] = B2[threadIdx.x];
    }
}

__device__ __forceinline__ void load_row(float (&x)[DD], const float* p, int r) {
    const float4* iv = (const float4*)(p + (long)r * DD);
#pragma unroll
    for (int j = 0; j < 16; j++) {
        float4 v = iv[j];
        x[4 * j] = v.x; x[4 * j + 1] = v.y; x[4 * j + 2] = v.z; x[4 * j + 3] = v.w;
    }
}
__device__ __forceinline__ void add_row(float (&x)[DD], const float* p, int r) {
    const float4* iv = (const float4*)(p + (long)r * DD);
#pragma unroll
    for (int j = 0; j < 16; j++) {
        float4 v = iv[j];
        x[4 * j] += v.x; x[4 * j + 1] += v.y; x[4 * j + 2] += v.z; x[4 * j + 3] += v.w;
    }
}
__device__ __forceinline__ void store_row(const float (&x)[DD], float* p, int r) {
    float4* ov = (float4*)(p + (long)r * DD);
#pragma unroll
    for (int j = 0; j < 16; j++)
        ov[j] = make_float4(x[4 * j], x[4 * j + 1], x[4 * j + 2], x[4 * j + 3]);
}

// ---------------- M = mlp_l(h) (first message pass) ----------------
__global__ __launch_bounds__(128, 2)
void mlp_kernel(const float* __restrict__ in,
                const float* __restrict__ W1, const float* __restrict__ b1,
                const float* __restrict__ W2, const float* __restrict__ b2,
                float* __restrict__ out, int n) {
    __shared__ float w1s[DD * DD], w2s[DD * DD], b1sh[DD], b2sh[DD];
    load_weights(w1s, w2s, b1sh, b2sh, W1, W2, b1, b2);
    __syncthreads();

    int r = blockIdx.x * blockDim.x + threadIdx.x;
    if (r >= n) return;
    float x[DD];
    load_row(x, in, r);
    stage64(x, w1s, b1sh, true);
    stage64(x, w2s, b2sh, false);
    store_row(x, out, r);
}

// ---- fused: H = mlp_a(h+G); M = mlp_b(H) ----
__global__ __launch_bounds__(128, 2)
void fused2_kernel(const float* __restrict__ h, const float* __restrict__ G,
                   const float* __restrict__ W1a, const float* __restrict__ b1a,
                   const float* __restrict__ W2a, const float* __restrict__ b2a,
                   const float* __restrict__ W1b, const float* __restrict__ b1b,
                   const float* __restrict__ W2b, const float* __restrict__ b2b,
                   float* __restrict__ H, float* __restrict__ M, int n) {
    __shared__ float w1s[DD * DD], w2s[DD * DD], b1sh[DD], b2sh[DD];
    load_weights(w1s, w2s, b1sh, b2sh, W1a, W2a, b1a, b2a);
    __syncthreads();

    int r = blockIdx.x * blockDim.x + threadIdx.x;
    bool act = r < n;
    float x[DD];
    if (act) {
        load_row(x, h, r);
        add_row(x, G, r);
        stage64(x, w1s, b1sh, true);
        stage64(x, w2s, b2sh, false);
        store_row(x, H, r);
    }
    __syncthreads();  // all smem reads done
    load_weights(w1s, w2s, b1sh, b2sh, W1b, W2b, b1b, b2b);
    __syncthreads();
    if (act) {
        stage64(x, w1s, b1sh, true);
        stage64(x, w2s, b2sh, false);
        store_row(x, M, r);
    }
}

// ---- fused final: out = mlp_c(h+G) @ Wf + bf ----
__global__ __launch_bounds__(128, 2)
void fused_final_kernel(const float* __restrict__ h, const float* __restrict__ G,
                        const float* __restrict__ W1, const float* __restrict__ b1,
                        const float* __restrict__ W2, const float* __restrict__ b2,
                        const float* __restrict__ Wf, const float* __restrict__ bf,
                        float* __restrict__ out, int n) {
    __shared__ float w1s[DD * DD], w2s[DD * DD], b1sh[DD], b2sh[DD];
    load_weights(w1s, w2s, b1sh, b2sh, W1, W2, b1, b2);
    __syncthreads();

    int r = blockIdx.x * blockDim.x + threadIdx.x;
    bool act = r < n;
    float x[DD];
    if (act) {
        load_row(x, h, r);
        add_row(x, G, r);
        stage64(x, w1s, b1sh, true);
        stage64(x, w2s, b2sh, false);
    }
    __syncthreads();
    {   // reload Wf into w1s
        const float4* wv = (const float4*)Wf;
        float4* s1 = (float4*)w1s;
        for (int i = threadIdx.x; i < DD * DD / 4; i += blockDim.x) s1[i] = wv[i];
        if (threadIdx.x < DD) b1sh[threadIdx.x] = bf[threadIdx.x];
    }
    __syncthreads();
    if (act) {
        stage64(x, w1s, b1sh, false);
        store_row(x, out, r);
    }
}

// ---------------- gather-side segment sum: G[v] = sum_{e: row=v} M[col_e] ----
// warp per node; half-warps process alternating edges with float4 loads.
__global__ __launch_bounds__(256)
void agg_kernel(const float* __restrict__ Msrc, float* __restrict__ G, int n) {
    int t = blockIdx.x * blockDim.x + threadIdx.x;
    int w = t >> 5;
    if (w >= n) return;
    int lane = t & 31;
    int half = lane >> 4;   // 0 or 1
    int l16 = lane & 15;    // column group (16 lanes x float4 = 64 floats)
    int s = g_rowptr[w];
    int e = g_rowptr[w + 1];
    float a0 = 0.f, a1 = 0.f, a2 = 0.f, a3 = 0.f;
    for (int j = s + half; j < e; j += 2) {
        int c = __ldg(&g_ecol[j]);
        float4 v = __ldg((const float4*)(Msrc + (long)c * DD) + l16);
        a0 += v.x; a1 += v.y; a2 += v.z; a3 += v.w;
    }
    a0 += __shfl_down_sync(0xffffffffu, a0, 16);
    a1 += __shfl_down_sync(0xffffffffu, a1, 16);
    a2 += __shfl_down_sync(0xffffffffu, a2, 16);
    a3 += __shfl_down_sync(0xffffffffu, a3, 16);
    if (half == 0)
        ((float4*)(G + (long)w * DD))[l16] = make_float4(a0, a1, a2, a3);
}

// ---------------- launch ----------------
extern "C" void kernel_launch(void* const* d_in, const int* in_sizes, int n_in,
                              void* d_out, int out_size) {
    const float* x  = (const float*)d_in[0];
    const int* eidx = (const int*)d_in[1];
    const float* W1 = (const float*)d_in[2];
    const float* b1 = (const float*)d_in[3];
    const float* W2 = (const float*)d_in[4];
    const float* b2 = (const float*)d_in[5];
    const float* Wf = (const float*)d_in[6];
    const float* bf = (const float*)d_in[7];

    int n = in_sizes[0] / DD;
    int E = in_sizes[1] / 2;
    const int* rows = eidx;      // destination (segment id)
    const int* cols = eidx + E;  // source (gather id)

    float *M, *G, *H, *H2;
    int* cnt;
    cudaGetSymbolAddress((void**)&M, g_M);
    cudaGetSymbolAddress((void**)&G, g_G);
    cudaGetSymbolAddress((void**)&H, g_H);
    cudaGetSymbolAddress((void**)&H2, g_H2);
    cudaGetSymbolAddress((void**)&cnt, g_cnt);

    const int TB = 256;
    int nb_e = (E + TB - 1) / TB;
    int nb_scan = (n + 1023) / 1024;
    int nb_mlp = (n + 127) / 128;
    int nb_agg = (n * 32 + TB - 1) / TB;

    // ---- CSR build (deterministic; captured into the graph) ----
    cudaMemsetAsync(cnt, 0, n * sizeof(int));
    hist_kernel<<<nb_e, TB>>>(rows, E);
    scan1_kernel<<<nb_scan, 1024>>>(n);
    scan2_kernel<<<1, 1024>>>(nb_scan);
    scan3_kernel<<<(n + 1 + TB - 1) / TB, TB>>>(n, E);
    cudaMemsetAsync(cnt, 0, n * sizeof(int));
    scatter_kernel<<<nb_e, TB>>>(rows, cols, E);

    // layer weight pointers
    const float* w1[LL]; const float* bb1[LL];
    const float* w2[LL]; const float* bb2[LL];
    for (int l = 0; l < LL; l++) {
        w1[l] = W1 + l * DD * DD; bb1[l] = b1 + l * DD;
        w2[l] = W2 + l * DD * DD; bb2[l] = b2 + l * DD;
    }

    // M0 = mlp_0(x)
    mlp_kernel<<<nb_mlp, 128>>>(x, w1[0], bb1[0], w2[0], bb2[0], M, n);
    // G0 = agg(M0)
    agg_kernel<<<nb_agg, TB>>>(M, G, n);
    // H1 = mlp_0(x + G0); M1 = mlp_1(H1)
    fused2_kernel<<<nb_mlp, 128>>>(x, G, w1[0], bb1[0], w2[0], bb2[0],
                                   w1[1], bb1[1], w2[1], bb2[1], H, M, n);
    // G1 = agg(M1)
    agg_kernel<<<nb_agg, TB>>>(M, G, n);
    // H2 = mlp_1(H1 + G1); M2 = mlp_2(H2)
    fused2_kernel<<<nb_mlp, 128>>>(H, G, w1[1], bb1[1], w2[1], bb2[1],
                                   w1[2], bb1[2], w2[2], bb2[2], H2, M, n);
    // G2 = agg(M2)
    agg_kernel<<<nb_agg, TB>>>(M, G, n);
    // out = mlp_2(H2 + G2) @ Wf + bf
    fused_final_kernel<<<nb_mlp, 128>>>(H2, G, w1[2], bb1[2], w2[2], bb2[2],
                                        Wf, bf, (float*)d_out, n);
}